// round 12
// baseline (speedup 1.0000x reference)
#include <cuda_runtime.h>
#include <cuda_bf16.h>
#include <stdint.h>
#include <math.h>

#define BB 8
#define NN 2048
#define NP 512
#define KW 16
#define ROWS (BB*NP*KW)   // 65536

// ---------------- scratch (static device globals; no allocation) ----------------
__device__ int   d_fidx[BB*NP];
__device__ int   d_knn[ROWS];
__device__ float d_S[3*ROWS*8];
__device__ float d_F0[ROWS*64];
__device__ float d_O0[ROWS*64];
__device__ float d_O1[ROWS*128];
__device__ float d_O2[ROWS*256];
__device__ float d_part[256*256*2];
__device__ float d_ab[512];
// pre-split banks, transposed: bh[n*KTOT + k], k = m*CIN + c
__device__ __nv_bfloat16 d_bh0[64*512],   d_bl0[64*512];
__device__ __nv_bfloat16 d_bh1[128*512],  d_bl1[128*512];
__device__ __nv_bfloat16 d_bh2[256*1024], d_bl2[256*1024];

__device__ __forceinline__ uint32_t smem_u32(const void* p){
    uint32_t a;
    asm("{ .reg .u64 t; cvta.to.shared.u64 t, %1; cvt.u32.u64 %0, t; }" : "=r"(a) : "l"(p));
    return a;
}
#define LDSM4(r0,r1,r2,r3,addr) \
    asm volatile("ldmatrix.sync.aligned.m8n8.x4.shared.b16 {%0,%1,%2,%3}, [%4];" \
        : "=r"(r0),"=r"(r1),"=r"(r2),"=r"(r3) : "r"(addr))
#define CP_ASYNC16(smem, gptr) \
    asm volatile("cp.async.cg.shared.global [%0], [%1], 16;" :: "r"(smem), "l"(gptr))
#define CP_COMMIT() asm volatile("cp.async.commit_group;" ::: "memory")
#define CP_WAIT0()  asm volatile("cp.async.wait_group 0;" ::: "memory")

// ---------------- fused: FPS (blocks 0-7) + bank split (blocks 8+) ----------------
__global__ void fps_bsplit_kernel(const float* __restrict__ xyz, float* __restrict__ out,
                                  const float* __restrict__ bank0, const float* __restrict__ bank1,
                                  const float* __restrict__ bank2){
    __shared__ float sx[NN], sy[NN], sz[NN];
    __shared__ float swv[8]; __shared__ int swi[8];
    __shared__ int sfid[NP];
    if (blockIdx.x >= 8){
        int i = (blockIdx.x - 8)*256 + threadIdx.x;
        float v; __nv_bfloat16 *ph, *pl; int n, k, KT;
        if (i < 32768){              // bank0: 512 x 64
            n = i % 64; k = i / 64; KT = 512; v = bank0[i]; ph = d_bh0; pl = d_bl0;
        } else if (i < 98304){       // bank1: 512 x 128
            int j = i - 32768; n = j % 128; k = j / 128; KT = 512; v = bank1[j]; ph = d_bh1; pl = d_bl1;
        } else {                     // bank2: 1024 x 256
            int j = i - 98304; n = j % 256; k = j / 256; KT = 1024; v = bank2[j]; ph = d_bh2; pl = d_bl2;
        }
        __nv_bfloat16 h = __float2bfloat16_rn(v);
        __nv_bfloat16 l = __float2bfloat16_rn(v - __bfloat162float(h));
        ph[(size_t)n*KT + k] = h;
        pl[(size_t)n*KT + k] = l;
        return;
    }
    int b = blockIdx.x, tid = threadIdx.x;
    const float* X = xyz + b*3*NN;
    for (int i = tid; i < NN; i += 256){ sx[i]=X[i]; sy[i]=X[NN+i]; sz[i]=X[2*NN+i]; }
    float dist[8];
    #pragma unroll
    for (int j=0;j<8;j++) dist[j] = 1e10f;
    __syncthreads();
    int far = 0;
    for (int it = 0; it < NP; ++it){
        if (tid == 0) sfid[it] = far;
        float cx = sx[far], cy = sy[far], cz = sz[far];
        float bv = -1.f; int bi = 0x7fffffff;
        #pragma unroll
        for (int j=0;j<8;j++){
            int n = j*256 + tid;
            float dx = __fsub_rn(sx[n],cx), dy = __fsub_rn(sy[n],cy), dz = __fsub_rn(sz[n],cz);
            float d  = __fadd_rn(__fadd_rn(__fmul_rn(dx,dx),__fmul_rn(dy,dy)),__fmul_rn(dz,dz));
            d = fminf(dist[j], d);
            dist[j] = d;
            if (d > bv) { bv = d; bi = n; }
        }
        #pragma unroll
        for (int off=16; off; off>>=1){
            float v2 = __shfl_down_sync(0xffffffffu, bv, off);
            int   i2 = __shfl_down_sync(0xffffffffu, bi, off);
            if (v2 > bv || (v2 == bv && i2 < bi)) { bv = v2; bi = i2; }
        }
        if ((tid & 31) == 0){ swv[tid>>5] = bv; swi[tid>>5] = bi; }
        __syncthreads();
        float fv = swv[0]; int fi = swi[0];
        #pragma unroll
        for (int w=1; w<8; w++){
            float v2 = swv[w]; int i2 = swi[w];
            if (v2 > fv || (v2 == fv && i2 < fi)) { fv = v2; fi = i2; }
        }
        far = fi;
        __syncthreads();
    }
    for (int p = tid; p < NP; p += 256){
        int n = sfid[p];
        d_fidx[b*NP + p] = n;
        out[(b*3+0)*NP + p] = sx[n];
        out[(b*3+1)*NP + p] = sy[n];
        out[(b*3+2)*NP + p] = sz[n];
    }
}

// ---------------- KNN: one warp per query, top-16 ascending (d, idx) ----------------
__global__ void knn_kernel(const float* __restrict__ xyz){
    int gw   = (blockIdx.x*blockDim.x + threadIdx.x) >> 5;
    int lane = threadIdx.x & 31;
    int b = gw >> 9, p = gw & 511;
    int qi = d_fidx[b*NP + p];
    const float* X = xyz + b*3*NN;
    float qx = X[qi], qy = X[NN+qi], qz = X[2*NN+qi];
    float qq = __fadd_rn(__fadd_rn(__fmul_rn(qx,qx),__fmul_rn(qy,qy)),__fmul_rn(qz,qz));
    float dk[16]; int ik[16];
    #pragma unroll
    for (int j=0;j<16;j++){ dk[j] = 3.4e38f; ik[j] = 0x7fffffff; }
    for (int c = 0; c < NN/32; c++){
        int n = c*32 + lane;
        float bx = X[n], by = X[NN+n], bz = X[2*NN+n];
        float ppn = __fadd_rn(__fadd_rn(__fmul_rn(bx,bx),__fmul_rn(by,by)),__fmul_rn(bz,bz));
        float d = (qq + ppn) - 2.0f*(qx*bx + qy*by + qz*bz);
        bool acc = (d < dk[15]) || (d == dk[15] && n < ik[15]);
        if (acc){
            int pos = 0;
            #pragma unroll
            for (int j=0;j<16;j++) pos += ((dk[j] < d) || (dk[j] == d && ik[j] < n)) ? 1 : 0;
            #pragma unroll
            for (int j=15;j>=0;--j){
                if (j > pos){ dk[j] = dk[j-1]; ik[j] = ik[j-1]; }
                else if (j == pos){ dk[j] = d; ik[j] = n; }
            }
        }
    }
    for (int r = 0; r < 16; r++){
        float v = dk[0]; int i = ik[0];
        #pragma unroll
        for (int off=16; off; off>>=1){
            float v2 = __shfl_xor_sync(0xffffffffu, v, off);
            int   i2 = __shfl_xor_sync(0xffffffffu, i, off);
            if (v2 < v || (v2 == v && i2 < i)) { v = v2; i = i2; }
        }
        if (lane == 0) d_knn[gw*16 + r] = i;
        if (ik[0] == i){
            #pragma unroll
            for (int j=0;j<15;j++){ dk[j] = dk[j+1]; ik[j] = ik[j+1]; }
            dk[15] = 3.4e38f; ik[15] = 0x7fffffff;
        }
    }
}

// ---------------- geometry + scores (fused) + feat gather + norm/X/Y outputs ----------------
__global__ void geomS_kernel(const float* __restrict__ xyz, const float* __restrict__ nr,
                             const float* __restrict__ Xa, const float* __restrict__ Ya,
                             const float* __restrict__ pts, float* out,
                             const float* __restrict__ w1_0, const float* __restrict__ b1_0,
                             const float* __restrict__ w2_0, const float* __restrict__ b2_0,
                             const float* __restrict__ w1_1, const float* __restrict__ b1_1,
                             const float* __restrict__ w2_1, const float* __restrict__ b2_1,
                             const float* __restrict__ w1_2, const float* __restrict__ b1_2,
                             const float* __restrict__ w2_2, const float* __restrict__ b2_2){
    int idx = blockIdx.x*128 + threadIdx.x;  // 65536 rows
    int b = idx >> 13;
    int p = (idx >> 4) & 511;
    int k = idx & 15;
    int n = d_knn[idx];
    int base = b*3*NN;
    float cx = out[(b*3+0)*NP + p], cy = out[(b*3+1)*NP + p], cz = out[(b*3+2)*NP + p];
    float gx = xyz[base+n] - cx, gy = xyz[base+NN+n] - cy, gz = xyz[base+2*NN+n] - cz;
    float nxv = nr[base+n], nyv = nr[base+NN+n], nzv = nr[base+2*NN+n];
    float Xx = Xa[base+n], Xy = Xa[base+NN+n], Xz = Xa[base+2*NN+n];
    float Yx = Ya[base+n], Yy = Ya[base+NN+n], Yz = Ya[base+2*NN+n];
    float dsq  = gx*gx + gy*gy + gz*gz;
    float dist = sqrtf(dsq + 1e-10f);
    float dmin = dist, dmax = dist;
    #pragma unroll
    for (int off=8; off; off>>=1){
        dmin = fminf(dmin, __shfl_xor_sync(0xffffffffu, dmin, off, 16));
        dmax = fmaxf(dmax, __shfl_xor_sync(0xffffffffu, dmax, off, 16));
    }
    float dn  = (dist - dmin) / ((dmax - dmin) + 1e-10f);
    float nn2 = sqrtf(gx*gx + gy*gy + gz*gz);
    const float INVPI = 0.318309886183790671f;
    float a0, a1, a2;
    {
        float dot = gx*nxv + gy*nyv + gz*nzv;
        float vn  = sqrtf(nxv*nxv + nyv*nyv + nzv*nzv);
        float c1  = dot / (nn2*vn + 1e-8f);
        a0 = acosf(fminf(1.f, fmaxf(-1.f, c1))) * INVPI;
    }
    {
        float dot = gx*Xx + gy*Xy + gz*Xz;
        float vn  = sqrtf(Xx*Xx + Xy*Xy + Xz*Xz);
        float c1  = dot / (nn2*vn + 1e-8f);
        a1 = acosf(fminf(1.f, fmaxf(-1.f, c1))) * INVPI;
    }
    {
        float dot = gx*Yx + gy*Yy + gz*Yz;
        float vn  = sqrtf(Yx*Yx + Yy*Yy + Yz*Yz);
        float c1  = dot / (nn2*vn + 1e-8f);
        a2 = acosf(fminf(1.f, fmaxf(-1.f, c1))) * INVPI;
    }
    float g[10];
    g[0]=gx; g[1]=gy; g[2]=gz; g[3]=dn; g[4]=nxv; g[5]=nyv; g[6]=nzv; g[7]=a0; g[8]=a1; g[9]=a2;

    const float* W1[3] = {w1_0, w1_1, w1_2};
    const float* B1[3] = {b1_0, b1_1, b1_2};
    const float* W2[3] = {w2_0, w2_1, w2_2};
    const float* B2[3] = {b2_0, b2_1, b2_2};
    #pragma unroll
    for (int l=0;l<3;l++){
        float h[16];
        #pragma unroll
        for (int j=0;j<16;j++){
            float acc = B1[l][j];
            #pragma unroll
            for (int q=0;q<10;q++) acc = fmaf(W1[l][j*10+q], g[q], acc);
            h[j] = fmaxf(acc, 0.f);
        }
        float t[8]; float mx = -3.4e38f;
        #pragma unroll
        for (int m=0;m<8;m++){
            float acc = B2[l][m];
            #pragma unroll
            for (int j=0;j<16;j++) acc = fmaf(W2[l][m*16+j], h[j], acc);
            t[m] = acc; mx = fmaxf(mx, acc);
        }
        float sum = 0.f;
        #pragma unroll
        for (int m=0;m<8;m++){ t[m] = expf(t[m] - mx); sum += t[m]; }
        float inv = 1.f / sum;
        #pragma unroll
        for (int m=0;m<8;m++) d_S[l*ROWS*8 + idx*8 + m] = t[m]*inv;
    }

    const float* P = pts + b*64*NN;
    float* F = d_F0 + idx*64;
    #pragma unroll 8
    for (int c=0;c<64;c++) F[c] = P[c*NN + n];
    if (k == 0){
        int o1 = 3*BB*NP;  // 12288
        out[1*o1 + (b*3+0)*NP+p] = nxv; out[1*o1 + (b*3+1)*NP+p] = nyv; out[1*o1 + (b*3+2)*NP+p] = nzv;
        out[2*o1 + (b*3+0)*NP+p] = Xx;  out[2*o1 + (b*3+1)*NP+p] = Xy;  out[2*o1 + (b*3+2)*NP+p] = Xz;
        out[3*o1 + (b*3+0)*NP+p] = Yx;  out[3*o1 + (b*3+1)*NP+p] = Yy;  out[3*o1 + (b*3+2)*NP+p] = Yz;
    }
}

// ---------------- A-resident split-bf16 mma.sync PAConv GEMM, cp.async B, ldmatrix ----------------
// C[row,o] = sum_m s[row,m] * (f(F) @ bank_m)[row,o]
// CTA: 256 rows x 64 cols, 8 warps (4 row x 2 col), warp tile 64x32, 64-wide K chunks.
#define BST 72   // halfword row stride for B tiles (64 k + 8 pad); 144B = 9x16B

template<int CIN, int COUT, bool USE_BN>
__global__ void __launch_bounds__(256) paconv_mma(
        const float* __restrict__ F, const float* __restrict__ S,
        const __nv_bfloat16* __restrict__ Bth, const __nv_bfloat16* __restrict__ Btl,
        const float* __restrict__ ab, float* __restrict__ O)
{
    constexpr int KTOT  = 8*CIN;
    constexpr int AST   = CIN + 8;       // halfword row stride for A
    constexpr int NCH   = CIN/64;        // 64-wide k-chunks per m
    constexpr int NITER = 8*NCH;

    extern __shared__ char smraw[];
    __nv_bfloat16* Ah = (__nv_bfloat16*)smraw;
    __nv_bfloat16* Al = Ah + 256*AST;
    __nv_bfloat16* Bhs = Al + 256*AST;        // 2 buffers of 64*BST
    __nv_bfloat16* Bls = Bhs + 2*64*BST;
    float* sS = (float*)(Bls + 2*64*BST);     // 256 x 8

    int tid = threadIdx.x;
    int wid = tid >> 5, lane = tid & 31;
    int wr = wid & 3;
    int wc = wid >> 2;
    int row0 = blockIdx.x * 256;
    int col0 = blockIdx.y * 64;
    int gr = lane >> 2;
    int qc = (lane & 3) * 2;
    int nB = tid & 63, kg = tid >> 6;    // B copy: 64 n-cols x 4 k-groups of 16

    // ---- ldmatrix per-thread addresses ----
    int rowinA = ((lane>>3)&1)*8 + (lane&7);
    int koffA  = (lane>>4)*8;
    uint32_t aAh[4], aAl[4];
    #pragma unroll
    for (int mt=0; mt<4; mt++){
        aAh[mt] = smem_u32(&Ah[(wr*64 + mt*16 + rowinA)*AST + koffA]);
        aAl[mt] = smem_u32(&Al[(wr*64 + mt*16 + rowinA)*AST + koffA]);
    }
    int rowinB = ((lane>>4)&1)*8 + (lane&7);
    int koffB  = ((lane>>3)&1)*8;
    uint32_t aBh[2], aBl[2];
    #pragma unroll
    for (int p=0; p<2; p++){
        aBh[p] = smem_u32(&Bhs[(wc*32 + p*16 + rowinB)*BST + koffB]);
        aBl[p] = smem_u32(&Bls[(wc*32 + p*16 + rowinB)*BST + koffB]);
    }
    const uint32_t BUFO = 64*BST*2;  // bytes per B buffer

    // cp.async dst/src bases for this thread
    uint32_t uBh = smem_u32(Bhs) + (uint32_t)nB*(BST*2) + (uint32_t)kg*32;
    uint32_t uBl = smem_u32(Bls) + (uint32_t)nB*(BST*2) + (uint32_t)kg*32;
    const __nv_bfloat16* gBh = Bth + (size_t)(col0 + nB)*KTOT + kg*16;
    const __nv_bfloat16* gBl = Btl + (size_t)(col0 + nB)*KTOT + kg*16;

    // ---- prologue: issue chunk 0 -> buffer 0 ----
    CP_ASYNC16(uBh,      gBh);
    CP_ASYNC16(uBh + 16, gBh + 8);
    CP_ASYNC16(uBl,      gBl);
    CP_ASYNC16(uBl + 16, gBl + 8);
    CP_COMMIT();

    // ---- stage S ----
    for (int i = tid; i < 2048; i += 256) sS[i] = S[(size_t)row0*8 + i];

    // ---- A fill once: thread tid owns row tid ----
    {
        const float* Fp = F + (size_t)(row0 + tid)*CIN;
        #pragma unroll
        for (int c = 0; c < CIN; c += 4){
            float4 v = *(const float4*)(Fp + c);
            if (USE_BN){
                v.x = fmaxf(fmaf(v.x, ab[c+0], ab[256+c+0]), 0.f);
                v.y = fmaxf(fmaf(v.y, ab[c+1], ab[256+c+1]), 0.f);
                v.z = fmaxf(fmaf(v.z, ab[c+2], ab[256+c+2]), 0.f);
                v.w = fmaxf(fmaf(v.w, ab[c+3], ab[256+c+3]), 0.f);
            }
            __nv_bfloat162 h01 = __floats2bfloat162_rn(v.x, v.y);
            __nv_bfloat162 h23 = __floats2bfloat162_rn(v.z, v.w);
            __nv_bfloat162 l01 = __floats2bfloat162_rn(
                v.x - __bfloat162float(__low2bfloat16(h01)),
                v.y - __bfloat162float(__high2bfloat16(h01)));
            __nv_bfloat162 l23 = __floats2bfloat162_rn(
                v.z - __bfloat162float(__low2bfloat16(h23)),
                v.w - __bfloat162float(__high2bfloat16(h23)));
            int off = tid*AST + c;
            *(__nv_bfloat162*)&Ah[off]   = h01;
            *(__nv_bfloat162*)&Ah[off+2] = h23;
            *(__nv_bfloat162*)&Al[off]   = l01;
            *(__nv_bfloat162*)&Al[off+2] = l23;
        }
    }

    float acc[4][4][4], acc2[4][4][4];
    #pragma unroll
    for (int i=0;i<4;i++)
        #pragma unroll
        for (int j=0;j<4;j++)
            #pragma unroll
            for (int q=0;q<4;q++){ acc[i][j][q] = 0.f; acc2[i][j][q] = 0.f; }

    CP_WAIT0();
    __syncthreads();

    int it = 0;
    for (int m = 0; m < 8; m++){
        for (int ci = 0; ci < NCH; ci++, it++){
            int nit = it + 1;
            if (nit < NITER){
                uint32_t dof = (nit & 1) ? BUFO : 0u;
                const __nv_bfloat16* sh = gBh + (size_t)nit*64;
                const __nv_bfloat16* sl = gBl + (size_t)nit*64;
                CP_ASYNC16(uBh + dof,      sh);
                CP_ASYNC16(uBh + dof + 16, sh + 8);
                CP_ASYNC16(uBl + dof,      sl);
                CP_ASYNC16(uBl + dof + 16, sl + 8);
                CP_COMMIT();
            }
            uint32_t bo = (it & 1) ? BUFO : 0u;
            #pragma unroll
            for (int kb = 0; kb < 64; kb += 16){
                uint32_t kA = (uint32_t)(ci*64 + kb)*2;
                uint32_t kB = (uint32_t)kb*2;
                uint32_t ah[4][4], al[4][4], bh[4][2], bl[4][2];
                #pragma unroll
                for (int mt=0; mt<4; mt++){
                    LDSM4(ah[mt][0], ah[mt][1], ah[mt][2], ah[mt][3], aAh[mt] + kA);
                    LDSM4(al[mt][0], al[mt][1], al[mt][2], al[mt][3], aAl[mt] + kA);
                }
                LDSM4(bh[0][0], bh[0][1], bh[1][0], bh[1][1], aBh[0] + bo + kB);
                LDSM4(bh[2][0], bh[2][1], bh[3][0], bh[3][1], aBh[1] + bo + kB);
                LDSM4(bl[0][0], bl[0][1], bl[1][0], bl[1][1], aBl[0] + bo + kB);
                LDSM4(bl[2][0], bl[2][1], bl[3][0], bl[3][1], aBl[1] + bo + kB);
                #pragma unroll
                for (int mt=0; mt<4; mt++)
                    #pragma unroll
                    for (int nt=0; nt<4; nt++){
                        float* d = acc[mt][nt];
                        asm volatile(
                          "mma.sync.aligned.m16n8k16.row.col.f32.bf16.bf16.f32 "
                          "{%0,%1,%2,%3}, {%4,%5,%6,%7}, {%8,%9}, {%0,%1,%2,%3};"
                          : "+f"(d[0]),"+f"(d[1]),"+f"(d[2]),"+f"(d[3])
                          : "r"(ah[mt][0]),"r"(ah[mt][1]),"r"(ah[mt][2]),"r"(ah[mt][3]),
                            "r"(bh[nt][0]),"r"(bh[nt][1]));
                        asm volatile(
                          "mma.sync.aligned.m16n8k16.row.col.f32.bf16.bf16.f32 "
                          "{%0,%1,%2,%3}, {%4,%5,%6,%7}, {%8,%9}, {%0,%1,%2,%3};"
                          : "+f"(d[0]),"+f"(d[1]),"+f"(d[2]),"+f"(d[3])
                          : "r"(ah[mt][0]),"r"(ah[mt][1]),"r"(ah[mt][2]),"r"(ah[mt][3]),
                            "r"(bl[nt][0]),"r"(bl[nt][1]));
                        asm volatile(
                          "mma.sync.aligned.m16n8k16.row.col.f32.bf16.bf16.f32 "
                          "{%0,%1,%2,%3}, {%4,%5,%6,%7}, {%8,%9}, {%0,%1,%2,%3};"
                          : "+f"(d[0]),"+f"(d[1]),"+f"(d[2]),"+f"(d[3])
                          : "r"(al[mt][0]),"r"(al[mt][1]),"r"(al[mt][2]),"r"(al[mt][3]),
                            "r"(bh[nt][0]),"r"(bh[nt][1]));
                    }
            }
            // ---- fold acc into acc2 with s[row, m] at end of m ----
            if (ci == NCH-1){
                #pragma unroll
                for (int mt=0; mt<4; mt++){
                    int r = wr*64 + mt*16 + gr;
                    float s0 = sS[r*8 + m];
                    float s1 = sS[(r+8)*8 + m];
                    #pragma unroll
                    for (int nt=0; nt<4; nt++){
                        acc2[mt][nt][0] = fmaf(s0, acc[mt][nt][0], acc2[mt][nt][0]);
                        acc2[mt][nt][1] = fmaf(s0, acc[mt][nt][1], acc2[mt][nt][1]);
                        acc2[mt][nt][2] = fmaf(s1, acc[mt][nt][2], acc2[mt][nt][2]);
                        acc2[mt][nt][3] = fmaf(s1, acc[mt][nt][3], acc2[mt][nt][3]);
                        acc[mt][nt][0]=0.f; acc[mt][nt][1]=0.f; acc[mt][nt][2]=0.f; acc[mt][nt][3]=0.f;
                    }
                }
            }
            if (nit < NITER) CP_WAIT0();
            __syncthreads();
        }
    }

    // ---- epilogue ----
    #pragma unroll
    for (int mt=0; mt<4; mt++){
        int r = row0 + wr*64 + mt*16 + gr;
        #pragma unroll
        for (int nt=0; nt<4; nt++){
            int c = col0 + wc*32 + nt*8 + qc;
            float* d = acc2[mt][nt];
            *(float2*)&O[(size_t)r*COUT + c]     = make_float2(d[0], d[1]);
            *(float2*)&O[(size_t)(r+8)*COUT + c] = make_float2(d[2], d[3]);
        }
    }
}

// ---------------- BN stats: deterministic two-stage ----------------
template<int C>
__global__ void bn_stats1(const float* __restrict__ O){
    __shared__ float sm1[256], sm2[256];
    int tid = threadIdx.x;
    float s1 = 0.f, s2 = 0.f;
    for (int i = blockIdx.x*256 + tid; i < ROWS*C; i += 65536){
        float v = O[i]; s1 += v; s2 += v*v;
    }
    sm1[tid] = s1; sm2[tid] = s2; __syncthreads();
    if (tid < C){
        for (int j = tid + C; j < 256; j += C){ s1 += sm1[j]; s2 += sm2[j]; }
        d_part[(blockIdx.x*C + tid)*2]   = s1;
        d_part[(blockIdx.x*C + tid)*2+1] = s2;
    }
}

template<int C>
__global__ void bn_stats2(const float* __restrict__ gamma, const float* __restrict__ beta){
    int c = threadIdx.x;
    double s1 = 0.0, s2 = 0.0;
    for (int j=0;j<256;j++){
        s1 += (double)d_part[(j*C + c)*2];
        s2 += (double)d_part[(j*C + c)*2 + 1];
    }
    double mean = s1 / 65536.0;
    double var  = s2 / 65536.0 - mean*mean;
    float a = (float)((double)gamma[c] / sqrt(var + 1e-5));
    d_ab[c]       = a;
    d_ab[256 + c] = beta[c] - (float)mean * a;
}

// ---------------- final max over K ----------------
__global__ void maxk_kernel(float* __restrict__ out){
    int idx = blockIdx.x*256 + threadIdx.x;
    int o = idx & 255; int p = (idx >> 8) & 511; int b = idx >> 17;
    const float* Ob = d_O2 + ((size_t)(b*NP + p)*KW)*256 + o;
    float m = -3.4e38f;
    #pragma unroll
    for (int k=0;k<16;k++) m = fmaxf(m, Ob[k*256]);
    out[4*3*BB*NP + (b*256 + o)*NP + p] = m;
}

// ---------------- launch ----------------
extern "C" void kernel_launch(void* const* d_in, const int* in_sizes, int n_in,
                              void* d_out, int out_size){
    const float* xyz   = (const float*)d_in[0];
    const float* nr    = (const float*)d_in[1];
    const float* Xa    = (const float*)d_in[2];
    const float* Ya    = (const float*)d_in[3];
    const float* pts   = (const float*)d_in[4];
    const float* w1_0  = (const float*)d_in[5];
    const float* b1_0  = (const float*)d_in[6];
    const float* w2_0  = (const float*)d_in[7];
    const float* b2_0  = (const float*)d_in[8];
    const float* bank0 = (const float*)d_in[9];
    const float* gam0  = (const float*)d_in[10];
    const float* bet0  = (const float*)d_in[11];
    const float* w1_1  = (const float*)d_in[12];
    const float* b1_1  = (const float*)d_in[13];
    const float* w2_1  = (const float*)d_in[14];
    const float* b2_1  = (const float*)d_in[15];
    const float* bank1 = (const float*)d_in[16];
    const float* gam1  = (const float*)d_in[17];
    const float* bet1  = (const float*)d_in[18];
    const float* w1_2  = (const float*)d_in[19];
    const float* b1_2  = (const float*)d_in[20];
    const float* w2_2  = (const float*)d_in[21];
    const float* b2_2  = (const float*)d_in[22];
    const float* bank2 = (const float*)d_in[23];
    float* out = (float*)d_out;

    float *pF0, *pO0, *pO1, *pO2, *pS, *pab;
    __nv_bfloat16 *pBH0, *pBL0, *pBH1, *pBL1, *pBH2, *pBL2;
    cudaGetSymbolAddress((void**)&pF0, d_F0);
    cudaGetSymbolAddress((void**)&pO0, d_O0);
    cudaGetSymbolAddress((void**)&pO1, d_O1);
    cudaGetSymbolAddress((void**)&pO2, d_O2);
    cudaGetSymbolAddress((void**)&pS,  d_S);
    cudaGetSymbolAddress((void**)&pab, d_ab);
    cudaGetSymbolAddress((void**)&pBH0, d_bh0);
    cudaGetSymbolAddress((void**)&pBL0, d_bl0);
    cudaGetSymbolAddress((void**)&pBH1, d_bh1);
    cudaGetSymbolAddress((void**)&pBL1, d_bl1);
    cudaGetSymbolAddress((void**)&pBH2, d_bh2);
    cudaGetSymbolAddress((void**)&pBL2, d_bl2);

    const int SMA64  = 2*(256*72*2)  + 2*(2*64*BST*2) + 8192;   // 155648
    const int SMA128 = 2*(256*136*2) + 2*(2*64*BST*2) + 8192;   // 221184
    cudaFuncSetAttribute(paconv_mma<64,64,false>,  cudaFuncAttributeMaxDynamicSharedMemorySize, SMA64);
    cudaFuncSetAttribute(paconv_mma<64,128,true>,  cudaFuncAttributeMaxDynamicSharedMemorySize, SMA64);
    cudaFuncSetAttribute(paconv_mma<128,256,true>, cudaFuncAttributeMaxDynamicSharedMemorySize, SMA128);

    fps_bsplit_kernel<<<1416,256>>>(xyz, out, bank0, bank1, bank2);  // 1 (fps + bank split fused)
    knn_kernel<<<512,256>>>(xyz);                                    // 2
    geomS_kernel<<<512,128>>>(xyz, nr, Xa, Ya, pts, out,
        w1_0,b1_0,w2_0,b2_0, w1_1,b1_1,w2_1,b2_1, w1_2,b1_2,w2_2,b2_2); // 3
    paconv_mma<64,64,false><<<dim3(256,1),256,SMA64>>>(pF0, pS, pBH0, pBL0, pab, pO0);  // 4 <- ncu
    bn_stats1<64><<<256,256>>>(pO0);                                 // 5
    bn_stats2<64><<<1,64>>>(gam0, bet0);                             // 6
    paconv_mma<64,128,true><<<dim3(256,2),256,SMA64>>>(pO0, pS + ROWS*8, pBH1, pBL1, pab, pO1); // 7
    bn_stats1<128><<<256,256>>>(pO1);                                // 8
    bn_stats2<128><<<1,128>>>(gam1, bet1);                           // 9
    paconv_mma<128,256,true><<<dim3(256,4),256,SMA128>>>(pO1, pS + 2*ROWS*8, pBH2, pBL2, pab, pO2); // 10
    maxk_kernel<<<4096,256>>>(out);                                  // 11
}

// round 13
// speedup vs baseline: 1.0361x; 1.0361x over previous
#include <cuda_runtime.h>
#include <cuda_bf16.h>
#include <stdint.h>
#include <math.h>

#define BB 8
#define NN 2048
#define NP 512
#define KW 16
#define ROWS (BB*NP*KW)   // 65536

// ---------------- scratch (static device globals; no allocation) ----------------
__device__ int   d_fidx[BB*NP];
__device__ int   d_knn[ROWS];
__device__ float d_S[3*ROWS*8];
__device__ float d_F0[ROWS*64];
__device__ float d_O0[ROWS*64];
__device__ float d_O1[ROWS*128];
__device__ float d_O2[ROWS*256];
__device__ float d_part[256*256*2];
__device__ float d_ab[512];
// pre-split banks, transposed: bh[n*KTOT + k], k = m*CIN + c
__device__ __nv_bfloat16 d_bh0[64*512],   d_bl0[64*512];
__device__ __nv_bfloat16 d_bh1[128*512],  d_bl1[128*512];
__device__ __nv_bfloat16 d_bh2[256*1024], d_bl2[256*1024];

__device__ __forceinline__ uint32_t smem_u32(const void* p){
    uint32_t a;
    asm("{ .reg .u64 t; cvta.to.shared.u64 t, %1; cvt.u32.u64 %0, t; }" : "=r"(a) : "l"(p));
    return a;
}
#define LDSM4(r0,r1,r2,r3,addr) \
    asm volatile("ldmatrix.sync.aligned.m8n8.x4.shared.b16 {%0,%1,%2,%3}, [%4];" \
        : "=r"(r0),"=r"(r1),"=r"(r2),"=r"(r3) : "r"(addr))
#define CP_ASYNC16(smem, gptr) \
    asm volatile("cp.async.cg.shared.global [%0], [%1], 16;" :: "r"(smem), "l"(gptr))
#define CP_COMMIT() asm volatile("cp.async.commit_group;" ::: "memory")
#define CP_WAIT0()  asm volatile("cp.async.wait_group 0;" ::: "memory")

// ---------------- fused: FPS (blocks 0-7) + bank split (blocks 8+) ----------------
__global__ void fps_bsplit_kernel(const float* __restrict__ xyz, float* __restrict__ out,
                                  const float* __restrict__ bank0, const float* __restrict__ bank1,
                                  const float* __restrict__ bank2){
    __shared__ float sx[NN], sy[NN], sz[NN];
    __shared__ float swv[8]; __shared__ int swi[8];
    __shared__ int sfid[NP];
    if (blockIdx.x >= 8){
        int i = (blockIdx.x - 8)*256 + threadIdx.x;
        float v; __nv_bfloat16 *ph, *pl; int n, k, KT;
        if (i < 32768){              // bank0: 512 x 64
            n = i % 64; k = i / 64; KT = 512; v = bank0[i]; ph = d_bh0; pl = d_bl0;
        } else if (i < 98304){       // bank1: 512 x 128
            int j = i - 32768; n = j % 128; k = j / 128; KT = 512; v = bank1[j]; ph = d_bh1; pl = d_bl1;
        } else {                     // bank2: 1024 x 256
            int j = i - 98304; n = j % 256; k = j / 256; KT = 1024; v = bank2[j]; ph = d_bh2; pl = d_bl2;
        }
        __nv_bfloat16 h = __float2bfloat16_rn(v);
        __nv_bfloat16 l = __float2bfloat16_rn(v - __bfloat162float(h));
        ph[(size_t)n*KT + k] = h;
        pl[(size_t)n*KT + k] = l;
        return;
    }
    int b = blockIdx.x, tid = threadIdx.x;
    const float* X = xyz + b*3*NN;
    for (int i = tid; i < NN; i += 256){ sx[i]=X[i]; sy[i]=X[NN+i]; sz[i]=X[2*NN+i]; }
    float dist[8];
    #pragma unroll
    for (int j=0;j<8;j++) dist[j] = 1e10f;
    __syncthreads();
    int far = 0;
    for (int it = 0; it < NP; ++it){
        if (tid == 0) sfid[it] = far;
        float cx = sx[far], cy = sy[far], cz = sz[far];
        float bv = -1.f; int bi = 0x7fffffff;
        #pragma unroll
        for (int j=0;j<8;j++){
            int n = j*256 + tid;
            float dx = __fsub_rn(sx[n],cx), dy = __fsub_rn(sy[n],cy), dz = __fsub_rn(sz[n],cz);
            float d  = __fadd_rn(__fadd_rn(__fmul_rn(dx,dx),__fmul_rn(dy,dy)),__fmul_rn(dz,dz));
            d = fminf(dist[j], d);
            dist[j] = d;
            if (d > bv) { bv = d; bi = n; }
        }
        #pragma unroll
        for (int off=16; off; off>>=1){
            float v2 = __shfl_down_sync(0xffffffffu, bv, off);
            int   i2 = __shfl_down_sync(0xffffffffu, bi, off);
            if (v2 > bv || (v2 == bv && i2 < bi)) { bv = v2; bi = i2; }
        }
        if ((tid & 31) == 0){ swv[tid>>5] = bv; swi[tid>>5] = bi; }
        __syncthreads();
        float fv = swv[0]; int fi = swi[0];
        #pragma unroll
        for (int w=1; w<8; w++){
            float v2 = swv[w]; int i2 = swi[w];
            if (v2 > fv || (v2 == fv && i2 < fi)) { fv = v2; fi = i2; }
        }
        far = fi;
        __syncthreads();
    }
    for (int p = tid; p < NP; p += 256){
        int n = sfid[p];
        d_fidx[b*NP + p] = n;
        out[(b*3+0)*NP + p] = sx[n];
        out[(b*3+1)*NP + p] = sy[n];
        out[(b*3+2)*NP + p] = sz[n];
    }
}

// ---------------- KNN: one warp per query, top-16 ascending (d, idx) ----------------
__global__ void knn_kernel(const float* __restrict__ xyz){
    int gw   = (blockIdx.x*blockDim.x + threadIdx.x) >> 5;
    int lane = threadIdx.x & 31;
    int b = gw >> 9, p = gw & 511;
    int qi = d_fidx[b*NP + p];
    const float* X = xyz + b*3*NN;
    float qx = X[qi], qy = X[NN+qi], qz = X[2*NN+qi];
    float qq = __fadd_rn(__fadd_rn(__fmul_rn(qx,qx),__fmul_rn(qy,qy)),__fmul_rn(qz,qz));
    float dk[16]; int ik[16];
    #pragma unroll
    for (int j=0;j<16;j++){ dk[j] = 3.4e38f; ik[j] = 0x7fffffff; }
    for (int c = 0; c < NN/32; c++){
        int n = c*32 + lane;
        float bx = X[n], by = X[NN+n], bz = X[2*NN+n];
        float ppn = __fadd_rn(__fadd_rn(__fmul_rn(bx,bx),__fmul_rn(by,by)),__fmul_rn(bz,bz));
        float d = (qq + ppn) - 2.0f*(qx*bx + qy*by + qz*bz);
        bool acc = (d < dk[15]) || (d == dk[15] && n < ik[15]);
        if (acc){
            int pos = 0;
            #pragma unroll
            for (int j=0;j<16;j++) pos += ((dk[j] < d) || (dk[j] == d && ik[j] < n)) ? 1 : 0;
            #pragma unroll
            for (int j=15;j>=0;--j){
                if (j > pos){ dk[j] = dk[j-1]; ik[j] = ik[j-1]; }
                else if (j == pos){ dk[j] = d; ik[j] = n; }
            }
        }
    }
    for (int r = 0; r < 16; r++){
        float v = dk[0]; int i = ik[0];
        #pragma unroll
        for (int off=16; off; off>>=1){
            float v2 = __shfl_xor_sync(0xffffffffu, v, off);
            int   i2 = __shfl_xor_sync(0xffffffffu, i, off);
            if (v2 < v || (v2 == v && i2 < i)) { v = v2; i = i2; }
        }
        if (lane == 0) d_knn[gw*16 + r] = i;
        if (ik[0] == i){
            #pragma unroll
            for (int j=0;j<15;j++){ dk[j] = dk[j+1]; ik[j] = ik[j+1]; }
            dk[15] = 3.4e38f; ik[15] = 0x7fffffff;
        }
    }
}

// ---------------- geometry + scores (fused) + feat gather + norm/X/Y outputs ----------------
__global__ void geomS_kernel(const float* __restrict__ xyz, const float* __restrict__ nr,
                             const float* __restrict__ Xa, const float* __restrict__ Ya,
                             const float* __restrict__ pts, float* out,
                             const float* __restrict__ w1_0, const float* __restrict__ b1_0,
                             const float* __restrict__ w2_0, const float* __restrict__ b2_0,
                             const float* __restrict__ w1_1, const float* __restrict__ b1_1,
                             const float* __restrict__ w2_1, const float* __restrict__ b2_1,
                             const float* __restrict__ w1_2, const float* __restrict__ b1_2,
                             const float* __restrict__ w2_2, const float* __restrict__ b2_2){
    int idx = blockIdx.x*128 + threadIdx.x;  // 65536 rows
    int b = idx >> 13;
    int p = (idx >> 4) & 511;
    int k = idx & 15;
    int n = d_knn[idx];
    int base = b*3*NN;
    float cx = out[(b*3+0)*NP + p], cy = out[(b*3+1)*NP + p], cz = out[(b*3+2)*NP + p];
    float gx = xyz[base+n] - cx, gy = xyz[base+NN+n] - cy, gz = xyz[base+2*NN+n] - cz;
    float nxv = nr[base+n], nyv = nr[base+NN+n], nzv = nr[base+2*NN+n];
    float Xx = Xa[base+n], Xy = Xa[base+NN+n], Xz = Xa[base+2*NN+n];
    float Yx = Ya[base+n], Yy = Ya[base+NN+n], Yz = Ya[base+2*NN+n];
    float dsq  = gx*gx + gy*gy + gz*gz;
    float dist = sqrtf(dsq + 1e-10f);
    float dmin = dist, dmax = dist;
    #pragma unroll
    for (int off=8; off; off>>=1){
        dmin = fminf(dmin, __shfl_xor_sync(0xffffffffu, dmin, off, 16));
        dmax = fmaxf(dmax, __shfl_xor_sync(0xffffffffu, dmax, off, 16));
    }
    float dn  = (dist - dmin) / ((dmax - dmin) + 1e-10f);
    float nn2 = sqrtf(gx*gx + gy*gy + gz*gz);
    const float INVPI = 0.318309886183790671f;
    float a0, a1, a2;
    {
        float dot = gx*nxv + gy*nyv + gz*nzv;
        float vn  = sqrtf(nxv*nxv + nyv*nyv + nzv*nzv);
        float c1  = dot / (nn2*vn + 1e-8f);
        a0 = acosf(fminf(1.f, fmaxf(-1.f, c1))) * INVPI;
    }
    {
        float dot = gx*Xx + gy*Xy + gz*Xz;
        float vn  = sqrtf(Xx*Xx + Xy*Xy + Xz*Xz);
        float c1  = dot / (nn2*vn + 1e-8f);
        a1 = acosf(fminf(1.f, fmaxf(-1.f, c1))) * INVPI;
    }
    {
        float dot = gx*Yx + gy*Yy + gz*Yz;
        float vn  = sqrtf(Yx*Yx + Yy*Yy + Yz*Yz);
        float c1  = dot / (nn2*vn + 1e-8f);
        a2 = acosf(fminf(1.f, fmaxf(-1.f, c1))) * INVPI;
    }
    float g[10];
    g[0]=gx; g[1]=gy; g[2]=gz; g[3]=dn; g[4]=nxv; g[5]=nyv; g[6]=nzv; g[7]=a0; g[8]=a1; g[9]=a2;

    const float* W1[3] = {w1_0, w1_1, w1_2};
    const float* B1[3] = {b1_0, b1_1, b1_2};
    const float* W2[3] = {w2_0, w2_1, w2_2};
    const float* B2[3] = {b2_0, b2_1, b2_2};
    #pragma unroll
    for (int l=0;l<3;l++){
        float h[16];
        #pragma unroll
        for (int j=0;j<16;j++){
            float acc = B1[l][j];
            #pragma unroll
            for (int q=0;q<10;q++) acc = fmaf(W1[l][j*10+q], g[q], acc);
            h[j] = fmaxf(acc, 0.f);
        }
        float t[8]; float mx = -3.4e38f;
        #pragma unroll
        for (int m=0;m<8;m++){
            float acc = B2[l][m];
            #pragma unroll
            for (int j=0;j<16;j++) acc = fmaf(W2[l][m*16+j], h[j], acc);
            t[m] = acc; mx = fmaxf(mx, acc);
        }
        float sum = 0.f;
        #pragma unroll
        for (int m=0;m<8;m++){ t[m] = expf(t[m] - mx); sum += t[m]; }
        float inv = 1.f / sum;
        #pragma unroll
        for (int m=0;m<8;m++) d_S[l*ROWS*8 + idx*8 + m] = t[m]*inv;
    }

    const float* P = pts + b*64*NN;
    float* F = d_F0 + idx*64;
    #pragma unroll 8
    for (int c=0;c<64;c++) F[c] = P[c*NN + n];
    if (k == 0){
        int o1 = 3*BB*NP;  // 12288
        out[1*o1 + (b*3+0)*NP+p] = nxv; out[1*o1 + (b*3+1)*NP+p] = nyv; out[1*o1 + (b*3+2)*NP+p] = nzv;
        out[2*o1 + (b*3+0)*NP+p] = Xx;  out[2*o1 + (b*3+1)*NP+p] = Xy;  out[2*o1 + (b*3+2)*NP+p] = Xz;
        out[3*o1 + (b*3+0)*NP+p] = Yx;  out[3*o1 + (b*3+1)*NP+p] = Yy;  out[3*o1 + (b*3+2)*NP+p] = Yz;
    }
}

// ---------------- A-resident split-bf16 mma.sync PAConv GEMM ----------------
// 512 threads / 16 warps (8 row x 2 col), warp tile 32x32; CTA 256 rows x 64 cols.
// A resident across all m; B (64-wide k-chunk) double-buffered via cp.async; s folded fp32.
#define BST 72   // halfword row stride for B tiles (64 k + 8 pad); 144B

template<int CIN, int COUT, bool USE_BN>
__global__ void __launch_bounds__(512) paconv_mma(
        const float* __restrict__ F, const float* __restrict__ S,
        const __nv_bfloat16* __restrict__ Bth, const __nv_bfloat16* __restrict__ Btl,
        const float* __restrict__ ab, float* __restrict__ O)
{
    constexpr int KTOT  = 8*CIN;
    constexpr int AST   = CIN + 8;       // halfword row stride for A
    constexpr int NCH   = CIN/64;        // 64-wide k-chunks per m
    constexpr int NITER = 8*NCH;

    extern __shared__ char smraw[];
    __nv_bfloat16* Ah = (__nv_bfloat16*)smraw;
    __nv_bfloat16* Al = Ah + 256*AST;
    __nv_bfloat16* Bhs = Al + 256*AST;        // 2 buffers of 64*BST
    __nv_bfloat16* Bls = Bhs + 2*64*BST;
    float* sS = (float*)(Bls + 2*64*BST);     // 256 x 8

    int tid = threadIdx.x;
    int wid = tid >> 5, lane = tid & 31;
    int wr = wid & 7;        // 8 row groups of 32
    int wc = wid >> 3;       // 2 col groups of 32
    int row0 = blockIdx.x * 256;
    int col0 = blockIdx.y * 64;
    int gr = lane >> 2;
    int qc = (lane & 3) * 2;
    int nB = tid & 63, kg = (tid >> 6) & 7;   // B copy: 64 n x 8 k-groups of 8

    // ---- ldmatrix per-thread addresses ----
    int rowinA = ((lane>>3)&1)*8 + (lane&7);
    int koffA  = (lane>>4)*8;
    uint32_t aAh[2], aAl[2];
    #pragma unroll
    for (int mt=0; mt<2; mt++){
        aAh[mt] = smem_u32(&Ah[(wr*32 + mt*16 + rowinA)*AST + koffA]);
        aAl[mt] = smem_u32(&Al[(wr*32 + mt*16 + rowinA)*AST + koffA]);
    }
    int rowinB = ((lane>>4)&1)*8 + (lane&7);
    int koffB  = ((lane>>3)&1)*8;
    uint32_t aBh[2], aBl[2];
    #pragma unroll
    for (int p=0; p<2; p++){
        aBh[p] = smem_u32(&Bhs[(wc*32 + p*16 + rowinB)*BST + koffB]);
        aBl[p] = smem_u32(&Bls[(wc*32 + p*16 + rowinB)*BST + koffB]);
    }
    const uint32_t BUFO = 64*BST*2;  // bytes per B buffer

    // cp.async: each thread copies 8 bf16 (16B) per array per chunk
    uint32_t uBh = smem_u32(Bhs) + (uint32_t)nB*(BST*2) + (uint32_t)kg*16;
    uint32_t uBl = smem_u32(Bls) + (uint32_t)nB*(BST*2) + (uint32_t)kg*16;
    const __nv_bfloat16* gBh = Bth + (size_t)(col0 + nB)*KTOT + kg*8;
    const __nv_bfloat16* gBl = Btl + (size_t)(col0 + nB)*KTOT + kg*8;

    // ---- prologue: chunk 0 -> buffer 0 ----
    CP_ASYNC16(uBh, gBh);
    CP_ASYNC16(uBl, gBl);
    CP_COMMIT();

    // ---- stage S ----
    for (int i = tid; i < 2048; i += 512) sS[i] = S[(size_t)row0*8 + i];

    // ---- A fill once: thread tid0 owns row tid0; halves split columns ----
    {
        int tid0 = tid & 255, half = tid >> 8;
        const float* Fp = F + (size_t)(row0 + tid0)*CIN;
        int c0 = half*(CIN/2);
        #pragma unroll
        for (int cc = 0; cc < CIN/2; cc += 4){
            int c = c0 + cc;
            float4 v = *(const float4*)(Fp + c);
            if (USE_BN){
                v.x = fmaxf(fmaf(v.x, ab[c+0], ab[256+c+0]), 0.f);
                v.y = fmaxf(fmaf(v.y, ab[c+1], ab[256+c+1]), 0.f);
                v.z = fmaxf(fmaf(v.z, ab[c+2], ab[256+c+2]), 0.f);
                v.w = fmaxf(fmaf(v.w, ab[c+3], ab[256+c+3]), 0.f);
            }
            __nv_bfloat162 h01 = __floats2bfloat162_rn(v.x, v.y);
            __nv_bfloat162 h23 = __floats2bfloat162_rn(v.z, v.w);
            __nv_bfloat162 l01 = __floats2bfloat162_rn(
                v.x - __bfloat162float(__low2bfloat16(h01)),
                v.y - __bfloat162float(__high2bfloat16(h01)));
            __nv_bfloat162 l23 = __floats2bfloat162_rn(
                v.z - __bfloat162float(__low2bfloat16(h23)),
                v.w - __bfloat162float(__high2bfloat16(h23)));
            int off = tid0*AST + c;
            *(__nv_bfloat162*)&Ah[off]   = h01;
            *(__nv_bfloat162*)&Ah[off+2] = h23;
            *(__nv_bfloat162*)&Al[off]   = l01;
            *(__nv_bfloat162*)&Al[off+2] = l23;
        }
    }

    float acc[2][4][4], acc2[2][4][4];
    #pragma unroll
    for (int i=0;i<2;i++)
        #pragma unroll
        for (int j=0;j<4;j++)
            #pragma unroll
            for (int q=0;q<4;q++){ acc[i][j][q] = 0.f; acc2[i][j][q] = 0.f; }

    CP_WAIT0();
    __syncthreads();

    int it = 0;
    for (int m = 0; m < 8; m++){
        for (int ci = 0; ci < NCH; ci++, it++){
            int nit = it + 1;
            if (nit < NITER){
                uint32_t dof = (nit & 1) ? BUFO : 0u;
                CP_ASYNC16(uBh + dof, gBh + (size_t)nit*64);
                CP_ASYNC16(uBl + dof, gBl + (size_t)nit*64);
                CP_COMMIT();
            }
            uint32_t bo = (it & 1) ? BUFO : 0u;
            #pragma unroll
            for (int kb = 0; kb < 64; kb += 16){
                uint32_t kA = (uint32_t)(ci*64 + kb)*2;
                uint32_t kB = (uint32_t)kb*2;
                uint32_t ah[2][4], al[2][4], bh[4][2], bl[4][2];
                #pragma unroll
                for (int mt=0; mt<2; mt++){
                    LDSM4(ah[mt][0], ah[mt][1], ah[mt][2], ah[mt][3], aAh[mt] + kA);
                    LDSM4(al[mt][0], al[mt][1], al[mt][2], al[mt][3], aAl[mt] + kA);
                }
                LDSM4(bh[0][0], bh[0][1], bh[1][0], bh[1][1], aBh[0] + bo + kB);
                LDSM4(bh[2][0], bh[2][1], bh[3][0], bh[3][1], aBh[1] + bo + kB);
                LDSM4(bl[0][0], bl[0][1], bl[1][0], bl[1][1], aBl[0] + bo + kB);
                LDSM4(bl[2][0], bl[2][1], bl[3][0], bl[3][1], aBl[1] + bo + kB);
                #pragma unroll
                for (int mt=0; mt<2; mt++)
                    #pragma unroll
                    for (int nt=0; nt<4; nt++){
                        float* d = acc[mt][nt];
                        asm volatile(
                          "mma.sync.aligned.m16n8k16.row.col.f32.bf16.bf16.f32 "
                          "{%0,%1,%2,%3}, {%4,%5,%6,%7}, {%8,%9}, {%0,%1,%2,%3};"
                          : "+f"(d[0]),"+f"(d[1]),"+f"(d[2]),"+f"(d[3])
                          : "r"(ah[mt][0]),"r"(ah[mt][1]),"r"(ah[mt][2]),"r"(ah[mt][3]),
                            "r"(bh[nt][0]),"r"(bh[nt][1]));
                        asm volatile(
                          "mma.sync.aligned.m16n8k16.row.col.f32.bf16.bf16.f32 "
                          "{%0,%1,%2,%3}, {%4,%5,%6,%7}, {%8,%9}, {%0,%1,%2,%3};"
                          : "+f"(d[0]),"+f"(d[1]),"+f"(d[2]),"+f"(d[3])
                          : "r"(ah[mt][0]),"r"(ah[mt][1]),"r"(ah[mt][2]),"r"(ah[mt][3]),
                            "r"(bl[nt][0]),"r"(bl[nt][1]));
                        asm volatile(
                          "mma.sync.aligned.m16n8k16.row.col.f32.bf16.bf16.f32 "
                          "{%0,%1,%2,%3}, {%4,%5,%6,%7}, {%8,%9}, {%0,%1,%2,%3};"
                          : "+f"(d[0]),"+f"(d[1]),"+f"(d[2]),"+f"(d[3])
                          : "r"(al[mt][0]),"r"(al[mt][1]),"r"(al[mt][2]),"r"(al[mt][3]),
                            "r"(bh[nt][0]),"r"(bh[nt][1]));
                    }
            }
            // ---- fold acc into acc2 with s[row, m] at end of m ----
            if (ci == NCH-1){
                #pragma unroll
                for (int mt=0; mt<2; mt++){
                    int r = wr*32 + mt*16 + gr;
                    float s0 = sS[r*8 + m];
                    float s1 = sS[(r+8)*8 + m];
                    #pragma unroll
                    for (int nt=0; nt<4; nt++){
                        acc2[mt][nt][0] = fmaf(s0, acc[mt][nt][0], acc2[mt][nt][0]);
                        acc2[mt][nt][1] = fmaf(s0, acc[mt][nt][1], acc2[mt][nt][1]);
                        acc2[mt][nt][2] = fmaf(s1, acc[mt][nt][2], acc2[mt][nt][2]);
                        acc2[mt][nt][3] = fmaf(s1, acc[mt][nt][3], acc2[mt][nt][3]);
                        acc[mt][nt][0]=0.f; acc[mt][nt][1]=0.f; acc[mt][nt][2]=0.f; acc[mt][nt][3]=0.f;
                    }
                }
            }
            if (nit < NITER) CP_WAIT0();
            __syncthreads();
        }
    }

    // ---- epilogue ----
    #pragma unroll
    for (int mt=0; mt<2; mt++){
        int r = row0 + wr*32 + mt*16 + gr;
        #pragma unroll
        for (int nt=0; nt<4; nt++){
            int c = col0 + wc*32 + nt*8 + qc;
            float* d = acc2[mt][nt];
            *(float2*)&O[(size_t)r*COUT + c]     = make_float2(d[0], d[1]);
            *(float2*)&O[(size_t)(r+8)*COUT + c] = make_float2(d[2], d[3]);
        }
    }
}

// ---------------- BN stats: deterministic two-stage ----------------
template<int C>
__global__ void bn_stats1(const float* __restrict__ O){
    __shared__ float sm1[256], sm2[256];
    int tid = threadIdx.x;
    float s1 = 0.f, s2 = 0.f;
    for (int i = blockIdx.x*256 + tid; i < ROWS*C; i += 65536){
        float v = O[i]; s1 += v; s2 += v*v;
    }
    sm1[tid] = s1; sm2[tid] = s2; __syncthreads();
    if (tid < C){
        for (int j = tid + C; j < 256; j += C){ s1 += sm1[j]; s2 += sm2[j]; }
        d_part[(blockIdx.x*C + tid)*2]   = s1;
        d_part[(blockIdx.x*C + tid)*2+1] = s2;
    }
}

template<int C>
__global__ void bn_stats2(const float* __restrict__ gamma, const float* __restrict__ beta){
    int c = threadIdx.x;
    double s1 = 0.0, s2 = 0.0;
    for (int j=0;j<256;j++){
        s1 += (double)d_part[(j*C + c)*2];
        s2 += (double)d_part[(j*C + c)*2 + 1];
    }
    double mean = s1 / 65536.0;
    double var  = s2 / 65536.0 - mean*mean;
    float a = (float)((double)gamma[c] / sqrt(var + 1e-5));
    d_ab[c]       = a;
    d_ab[256 + c] = beta[c] - (float)mean * a;
}

// ---------------- final max over K ----------------
__global__ void maxk_kernel(float* __restrict__ out){
    int idx = blockIdx.x*256 + threadIdx.x;
    int o = idx & 255; int p = (idx >> 8) & 511; int b = idx >> 17;
    const float* Ob = d_O2 + ((size_t)(b*NP + p)*KW)*256 + o;
    float m = -3.4e38f;
    #pragma unroll
    for (int k=0;k<16;k++) m = fmaxf(m, Ob[k*256]);
    out[4*3*BB*NP + (b*256 + o)*NP + p] = m;
}

// ---------------- launch ----------------
extern "C" void kernel_launch(void* const* d_in, const int* in_sizes, int n_in,
                              void* d_out, int out_size){
    const float* xyz   = (const float*)d_in[0];
    const float* nr    = (const float*)d_in[1];
    const float* Xa    = (const float*)d_in[2];
    const float* Ya    = (const float*)d_in[3];
    const float* pts   = (const float*)d_in[4];
    const float* w1_0  = (const float*)d_in[5];
    const float* b1_0  = (const float*)d_in[6];
    const float* w2_0  = (const float*)d_in[7];
    const float* b2_0  = (const float*)d_in[8];
    const float* bank0 = (const float*)d_in[9];
    const float* gam0  = (const float*)d_in[10];
    const float* bet0  = (const float*)d_in[11];
    const float* w1_1  = (const float*)d_in[12];
    const float* b1_1  = (const float*)d_in[13];
    const float* w2_1  = (const float*)d_in[14];
    const float* b2_1  = (const float*)d_in[15];
    const float* bank1 = (const float*)d_in[16];
    const float* gam1  = (const float*)d_in[17];
    const float* bet1  = (const float*)d_in[18];
    const float* w1_2  = (const float*)d_in[19];
    const float* b1_2  = (const float*)d_in[20];
    const float* w2_2  = (const float*)d_in[21];
    const float* b2_2  = (const float*)d_in[22];
    const float* bank2 = (const float*)d_in[23];
    float* out = (float*)d_out;

    float *pF0, *pO0, *pO1, *pO2, *pS, *pab;
    __nv_bfloat16 *pBH0, *pBL0, *pBH1, *pBL1, *pBH2, *pBL2;
    cudaGetSymbolAddress((void**)&pF0, d_F0);
    cudaGetSymbolAddress((void**)&pO0, d_O0);
    cudaGetSymbolAddress((void**)&pO1, d_O1);
    cudaGetSymbolAddress((void**)&pO2, d_O2);
    cudaGetSymbolAddress((void**)&pS,  d_S);
    cudaGetSymbolAddress((void**)&pab, d_ab);
    cudaGetSymbolAddress((void**)&pBH0, d_bh0);
    cudaGetSymbolAddress((void**)&pBL0, d_bl0);
    cudaGetSymbolAddress((void**)&pBH1, d_bh1);
    cudaGetSymbolAddress((void**)&pBL1, d_bl1);
    cudaGetSymbolAddress((void**)&pBH2, d_bh2);
    cudaGetSymbolAddress((void**)&pBL2, d_bl2);

    const int SMA64  = 2*(256*72*2)  + 2*(2*64*BST*2) + 8192;   // 155648
    const int SMA128 = 2*(256*136*2) + 2*(2*64*BST*2) + 8192;   // 221184
    cudaFuncSetAttribute(paconv_mma<64,64,false>,  cudaFuncAttributeMaxDynamicSharedMemorySize, SMA64);
    cudaFuncSetAttribute(paconv_mma<64,128,true>,  cudaFuncAttributeMaxDynamicSharedMemorySize, SMA64);
    cudaFuncSetAttribute(paconv_mma<128,256,true>, cudaFuncAttributeMaxDynamicSharedMemorySize, SMA128);

    fps_bsplit_kernel<<<1416,256>>>(xyz, out, bank0, bank1, bank2);  // 1 (fps + bank split fused)
    knn_kernel<<<512,256>>>(xyz);                                    // 2
    geomS_kernel<<<512,128>>>(xyz, nr, Xa, Ya, pts, out,
        w1_0,b1_0,w2_0,b2_0, w1_1,b1_1,w2_1,b2_1, w1_2,b1_2,w2_2,b2_2); // 3
    paconv_mma<64,64,false><<<dim3(256,1),512,SMA64>>>(pF0, pS, pBH0, pBL0, pab, pO0);  // 4 <- ncu
    bn_stats1<64><<<256,256>>>(pO0);                                 // 5
    bn_stats2<64><<<1,64>>>(gam0, bet0);                             // 6
    paconv_mma<64,128,true><<<dim3(256,2),512,SMA64>>>(pO0, pS + ROWS*8, pBH1, pBL1, pab, pO1); // 7
    bn_stats1<128><<<256,256>>>(pO1);                                // 8
    bn_stats2<128><<<1,128>>>(gam1, bet1);                           // 9
    paconv_mma<128,256,true><<<dim3(256,4),512,SMA128>>>(pO1, pS + 2*ROWS*8, pBH2, pBL2, pab, pO2); // 10
    maxk_kernel<<<4096,256>>>(out);                                  // 11
}

// round 15
// speedup vs baseline: 1.0749x; 1.0375x over previous
#include <cuda_runtime.h>
#include <cuda_bf16.h>
#include <stdint.h>
#include <math.h>

#define BB 8
#define NN 2048
#define NP 512
#define KW 16
#define ROWS (BB*NP*KW)   // 65536

// ---------------- scratch (static device globals; no allocation) ----------------
__device__ int   d_fidx[BB*NP];
__device__ int   d_knn[ROWS];
__device__ float d_S[3*ROWS*8];
__device__ float d_F0[ROWS*64];
__device__ float d_O0[ROWS*64];
__device__ float d_O1[ROWS*128];
__device__ float d_part[256*256*2];
__device__ float d_ab[512];
__device__ float d_ptsT[BB*NN*64];
// pre-split banks, transposed: bh[n*KTOT + k], k = m*CIN + c
__device__ __nv_bfloat16 d_bh0[64*512],   d_bl0[64*512];
__device__ __nv_bfloat16 d_bh1[128*512],  d_bl1[128*512];
__device__ __nv_bfloat16 d_bh2[256*1024], d_bl2[256*1024];

__device__ __forceinline__ uint32_t smem_u32(const void* p){
    uint32_t a;
    asm("{ .reg .u64 t; cvta.to.shared.u64 t, %1; cvt.u32.u64 %0, t; }" : "=r"(a) : "l"(p));
    return a;
}
#define LDSM4(r0,r1,r2,r3,addr) \
    asm volatile("ldmatrix.sync.aligned.m8n8.x4.shared.b16 {%0,%1,%2,%3}, [%4];" \
        : "=r"(r0),"=r"(r1),"=r"(r2),"=r"(r3) : "r"(addr))
#define CP_ASYNC16(smem, gptr) \
    asm volatile("cp.async.cg.shared.global [%0], [%1], 16;" :: "r"(smem), "l"(gptr))
#define CP_COMMIT() asm volatile("cp.async.commit_group;" ::: "memory")
#define CP_WAIT0()  asm volatile("cp.async.wait_group 0;" ::: "memory")

// ---------------- fused: FPS (blocks 0-7) + bank split (blocks 8+) ----------------
__global__ void fps_bsplit_kernel(const float* __restrict__ xyz, float* __restrict__ out,
                                  const float* __restrict__ bank0, const float* __restrict__ bank1,
                                  const float* __restrict__ bank2){
    __shared__ float sx[NN], sy[NN], sz[NN];
    __shared__ float swv[8]; __shared__ int swi[8];
    __shared__ int sfid[NP];
    if (blockIdx.x >= 8){
        int i = (blockIdx.x - 8)*256 + threadIdx.x;
        float v; __nv_bfloat16 *ph, *pl; int n, k, KT;
        if (i < 32768){              // bank0: 512 x 64
            n = i % 64; k = i / 64; KT = 512; v = bank0[i]; ph = d_bh0; pl = d_bl0;
        } else if (i < 98304){       // bank1: 512 x 128
            int j = i - 32768; n = j % 128; k = j / 128; KT = 512; v = bank1[j]; ph = d_bh1; pl = d_bl1;
        } else {                     // bank2: 1024 x 256
            int j = i - 98304; n = j % 256; k = j / 256; KT = 1024; v = bank2[j]; ph = d_bh2; pl = d_bl2;
        }
        __nv_bfloat16 h = __float2bfloat16_rn(v);
        __nv_bfloat16 l = __float2bfloat16_rn(v - __bfloat162float(h));
        ph[(size_t)n*KT + k] = h;
        pl[(size_t)n*KT + k] = l;
        return;
    }
    int b = blockIdx.x, tid = threadIdx.x;
    const float* X = xyz + b*3*NN;
    for (int i = tid; i < NN; i += 256){ sx[i]=X[i]; sy[i]=X[NN+i]; sz[i]=X[2*NN+i]; }
    float dist[8];
    #pragma unroll
    for (int j=0;j<8;j++) dist[j] = 1e10f;
    __syncthreads();
    int far = 0;
    for (int it = 0; it < NP; ++it){
        if (tid == 0) sfid[it] = far;
        float cx = sx[far], cy = sy[far], cz = sz[far];
        float bv = -1.f; int bi = 0x7fffffff;
        #pragma unroll
        for (int j=0;j<8;j++){
            int n = j*256 + tid;
            float dx = __fsub_rn(sx[n],cx), dy = __fsub_rn(sy[n],cy), dz = __fsub_rn(sz[n],cz);
            float d  = __fadd_rn(__fadd_rn(__fmul_rn(dx,dx),__fmul_rn(dy,dy)),__fmul_rn(dz,dz));
            d = fminf(dist[j], d);
            dist[j] = d;
            if (d > bv) { bv = d; bi = n; }
        }
        #pragma unroll
        for (int off=16; off; off>>=1){
            float v2 = __shfl_down_sync(0xffffffffu, bv, off);
            int   i2 = __shfl_down_sync(0xffffffffu, bi, off);
            if (v2 > bv || (v2 == bv && i2 < bi)) { bv = v2; bi = i2; }
        }
        if ((tid & 31) == 0){ swv[tid>>5] = bv; swi[tid>>5] = bi; }
        __syncthreads();
        float fv = swv[0]; int fi = swi[0];
        #pragma unroll
        for (int w=1; w<8; w++){
            float v2 = swv[w]; int i2 = swi[w];
            if (v2 > fv || (v2 == fv && i2 < fi)) { fv = v2; fi = i2; }
        }
        far = fi;
        __syncthreads();
    }
    for (int p = tid; p < NP; p += 256){
        int n = sfid[p];
        d_fidx[b*NP + p] = n;
        out[(b*3+0)*NP + p] = sx[n];
        out[(b*3+1)*NP + p] = sy[n];
        out[(b*3+2)*NP + p] = sz[n];
    }
}

// ---------------- pts transpose: [b][c][n] -> [b][n][c] (smem tiled) ----------------
__global__ void ptsT_kernel(const float* __restrict__ pts){
    __shared__ float t[64][33];
    int b = blockIdx.y;
    int n0 = blockIdx.x*32;
    int tx = threadIdx.x & 31, ty = threadIdx.x >> 5;   // 8 c-rows per pass
    const float* P = pts + (size_t)b*64*NN;
    #pragma unroll
    for (int cc = 0; cc < 8; cc++){
        int c = cc*8 + ty;
        t[c][tx] = P[(size_t)c*NN + n0 + tx];
    }
    __syncthreads();
    int cw = threadIdx.x & 63, j = threadIdx.x >> 6;    // 4 n per pass
    float* D = d_ptsT + ((size_t)b*NN + n0)*64;
    #pragma unroll
    for (int nn = 0; nn < 8; nn++){
        int n = nn*4 + j;
        D[(size_t)n*64 + cw] = t[cw][n];
    }
}

// ---------------- KNN: one warp per query, top-16 ascending (d, idx) ----------------
__global__ void knn_kernel(const float* __restrict__ xyz){
    int gw   = (blockIdx.x*blockDim.x + threadIdx.x) >> 5;
    int lane = threadIdx.x & 31;
    int b = gw >> 9, p = gw & 511;
    int qi = d_fidx[b*NP + p];
    const float* X = xyz + b*3*NN;
    float qx = X[qi], qy = X[NN+qi], qz = X[2*NN+qi];
    float qq = __fadd_rn(__fadd_rn(__fmul_rn(qx,qx),__fmul_rn(qy,qy)),__fmul_rn(qz,qz));
    float dk[16]; int ik[16];
    #pragma unroll
    for (int j=0;j<16;j++){ dk[j] = 3.4e38f; ik[j] = 0x7fffffff; }
    for (int c = 0; c < NN/32; c++){
        int n = c*32 + lane;
        float bx = X[n], by = X[NN+n], bz = X[2*NN+n];
        float ppn = __fadd_rn(__fadd_rn(__fmul_rn(bx,bx),__fmul_rn(by,by)),__fmul_rn(bz,bz));
        float d = (qq + ppn) - 2.0f*(qx*bx + qy*by + qz*bz);
        bool acc = (d < dk[15]) || (d == dk[15] && n < ik[15]);
        if (acc){
            int pos = 0;
            #pragma unroll
            for (int j=0;j<16;j++) pos += ((dk[j] < d) || (dk[j] == d && ik[j] < n)) ? 1 : 0;
            #pragma unroll
            for (int j=15;j>=0;--j){
                if (j > pos){ dk[j] = dk[j-1]; ik[j] = ik[j-1]; }
                else if (j == pos){ dk[j] = d; ik[j] = n; }
            }
        }
    }
    for (int r = 0; r < 16; r++){
        float v = dk[0]; int i = ik[0];
        #pragma unroll
        for (int off=16; off; off>>=1){
            float v2 = __shfl_xor_sync(0xffffffffu, v, off);
            int   i2 = __shfl_xor_sync(0xffffffffu, i, off);
            if (v2 < v || (v2 == v && i2 < i)) { v = v2; i = i2; }
        }
        if (lane == 0) d_knn[gw*16 + r] = i;
        if (ik[0] == i){
            #pragma unroll
            for (int j=0;j<15;j++){ dk[j] = dk[j+1]; ik[j] = ik[j+1]; }
            dk[15] = 3.4e38f; ik[15] = 0x7fffffff;
        }
    }
}

// ---------------- geometry + scores (fused) + feat gather + norm/X/Y outputs ----------------
__global__ void geomS_kernel(const float* __restrict__ xyz, const float* __restrict__ nr,
                             const float* __restrict__ Xa, const float* __restrict__ Ya,
                             float* out,
                             const float* __restrict__ w1_0, const float* __restrict__ b1_0,
                             const float* __restrict__ w2_0, const float* __restrict__ b2_0,
                             const float* __restrict__ w1_1, const float* __restrict__ b1_1,
                             const float* __restrict__ w2_1, const float* __restrict__ b2_1,
                             const float* __restrict__ w1_2, const float* __restrict__ b1_2,
                             const float* __restrict__ w2_2, const float* __restrict__ b2_2){
    int idx = blockIdx.x*128 + threadIdx.x;  // 65536 rows
    int b = idx >> 13;
    int p = (idx >> 4) & 511;
    int k = idx & 15;
    int n = d_knn[idx];
    int base = b*3*NN;
    float cx = out[(b*3+0)*NP + p], cy = out[(b*3+1)*NP + p], cz = out[(b*3+2)*NP + p];
    float gx = xyz[base+n] - cx, gy = xyz[base+NN+n] - cy, gz = xyz[base+2*NN+n] - cz;
    float nxv = nr[base+n], nyv = nr[base+NN+n], nzv = nr[base+2*NN+n];
    float Xx = Xa[base+n], Xy = Xa[base+NN+n], Xz = Xa[base+2*NN+n];
    float Yx = Ya[base+n], Yy = Ya[base+NN+n], Yz = Ya[base+2*NN+n];
    float dsq  = gx*gx + gy*gy + gz*gz;
    float dist = sqrtf(dsq + 1e-10f);
    float dmin = dist, dmax = dist;
    #pragma unroll
    for (int off=8; off; off>>=1){
        dmin = fminf(dmin, __shfl_xor_sync(0xffffffffu, dmin, off, 16));
        dmax = fmaxf(dmax, __shfl_xor_sync(0xffffffffu, dmax, off, 16));
    }
    float dn  = (dist - dmin) / ((dmax - dmin) + 1e-10f);
    float nn2 = sqrtf(gx*gx + gy*gy + gz*gz);
    const float INVPI = 0.318309886183790671f;
    float a0, a1, a2;
    {
        float dot = gx*nxv + gy*nyv + gz*nzv;
        float vn  = sqrtf(nxv*nxv + nyv*nyv + nzv*nzv);
        float c1  = dot / (nn2*vn + 1e-8f);
        a0 = acosf(fminf(1.f, fmaxf(-1.f, c1))) * INVPI;
    }
    {
        float dot = gx*Xx + gy*Xy + gz*Xz;
        float vn  = sqrtf(Xx*Xx + Xy*Xy + Xz*Xz);
        float c1  = dot / (nn2*vn + 1e-8f);
        a1 = acosf(fminf(1.f, fmaxf(-1.f, c1))) * INVPI;
    }
    {
        float dot = gx*Yx + gy*Yy + gz*Yz;
        float vn  = sqrtf(Yx*Yx + Yy*Yy + Yz*Yz);
        float c1  = dot / (nn2*vn + 1e-8f);
        a2 = acosf(fminf(1.f, fmaxf(-1.f, c1))) * INVPI;
    }
    float g[10];
    g[0]=gx; g[1]=gy; g[2]=gz; g[3]=dn; g[4]=nxv; g[5]=nyv; g[6]=nzv; g[7]=a0; g[8]=a1; g[9]=a2;

    const float* W1[3] = {w1_0, w1_1, w1_2};
    const float* B1[3] = {b1_0, b1_1, b1_2};
    const float* W2[3] = {w2_0, w2_1, w2_2};
    const float* B2[3] = {b2_0, b2_1, b2_2};
    #pragma unroll
    for (int l=0;l<3;l++){
        float h[16];
        #pragma unroll
        for (int j=0;j<16;j++){
            float acc = B1[l][j];
            #pragma unroll
            for (int q=0;q<10;q++) acc = fmaf(W1[l][j*10+q], g[q], acc);
            h[j] = fmaxf(acc, 0.f);
        }
        float t[8]; float mx = -3.4e38f;
        #pragma unroll
        for (int m=0;m<8;m++){
            float acc = B2[l][m];
            #pragma unroll
            for (int j=0;j<16;j++) acc = fmaf(W2[l][m*16+j], h[j], acc);
            t[m] = acc; mx = fmaxf(mx, acc);
        }
        float sum = 0.f;
        #pragma unroll
        for (int m=0;m<8;m++){ t[m] = expf(t[m] - mx); sum += t[m]; }
        float inv = 1.f / sum;
        #pragma unroll
        for (int m=0;m<8;m++) d_S[l*ROWS*8 + idx*8 + m] = t[m]*inv;
    }

    // feature gather from transposed pts: contiguous
    const float4* PT = (const float4*)(d_ptsT + ((size_t)b*NN + n)*64);
    float4* F4 = (float4*)(d_F0 + (size_t)idx*64);
    #pragma unroll
    for (int c=0;c<16;c++) F4[c] = PT[c];
    if (k == 0){
        int o1 = 3*BB*NP;  // 12288
        out[1*o1 + (b*3+0)*NP+p] = nxv; out[1*o1 + (b*3+1)*NP+p] = nyv; out[1*o1 + (b*3+2)*NP+p] = nzv;
        out[2*o1 + (b*3+0)*NP+p] = Xx;  out[2*o1 + (b*3+1)*NP+p] = Xy;  out[2*o1 + (b*3+2)*NP+p] = Xz;
        out[3*o1 + (b*3+0)*NP+p] = Yx;  out[3*o1 + (b*3+1)*NP+p] = Yy;  out[3*o1 + (b*3+2)*NP+p] = Yz;
    }
}

// ---------------- A-resident split-bf16 mma.sync PAConv GEMM ----------------
// 512 threads / 16 warps (8 row x 2 col), warp tile 32x32; CTA 256 rows x 64 cols.
// FUSE_MAX: reduce over K(=16 rows per p) in-register, write maxes directly to out.
#define BST 72   // halfword row stride for B tiles (64 k + 8 pad); 144B

template<int CIN, int COUT, bool USE_BN, bool FUSE_MAX>
__global__ void __launch_bounds__(512) paconv_mma(
        const float* __restrict__ F, const float* __restrict__ S,
        const __nv_bfloat16* __restrict__ Bth, const __nv_bfloat16* __restrict__ Btl,
        const float* __restrict__ ab, float* __restrict__ O)
{
    constexpr int KTOT  = 8*CIN;
    constexpr int AST   = CIN + 8;       // halfword row stride for A
    constexpr int NCH   = CIN/64;        // 64-wide k-chunks per m
    constexpr int NITER = 8*NCH;

    extern __shared__ char smraw[];
    __nv_bfloat16* Ah = (__nv_bfloat16*)smraw;
    __nv_bfloat16* Al = Ah + 256*AST;
    __nv_bfloat16* Bhs = Al + 256*AST;        // 2 buffers of 64*BST
    __nv_bfloat16* Bls = Bhs + 2*64*BST;
    float* sS = (float*)(Bls + 2*64*BST);     // 256 x 8

    int tid = threadIdx.x;
    int wid = tid >> 5, lane = tid & 31;
    int wr = wid & 7;        // 8 row groups of 32
    int wc = wid >> 3;       // 2 col groups of 32
    int row0 = blockIdx.x * 256;
    int col0 = blockIdx.y * 64;
    int gr = lane >> 2;
    int qc = (lane & 3) * 2;
    int nB = tid & 63, kg = (tid >> 6) & 7;   // B copy: 64 n x 8 k-groups of 8

    // ---- ldmatrix per-thread addresses ----
    int rowinA = ((lane>>3)&1)*8 + (lane&7);
    int koffA  = (lane>>4)*8;
    uint32_t aAh[2], aAl[2];
    #pragma unroll
    for (int mt=0; mt<2; mt++){
        aAh[mt] = smem_u32(&Ah[(wr*32 + mt*16 + rowinA)*AST + koffA]);
        aAl[mt] = smem_u32(&Al[(wr*32 + mt*16 + rowinA)*AST + koffA]);
    }
    int rowinB = ((lane>>4)&1)*8 + (lane&7);
    int koffB  = ((lane>>3)&1)*8;
    uint32_t aBh[2], aBl[2];
    #pragma unroll
    for (int p=0; p<2; p++){
        aBh[p] = smem_u32(&Bhs[(wc*32 + p*16 + rowinB)*BST + koffB]);
        aBl[p] = smem_u32(&Bls[(wc*32 + p*16 + rowinB)*BST + koffB]);
    }
    const uint32_t BUFO = 64*BST*2;  // bytes per B buffer

    // cp.async: each thread copies 8 bf16 (16B) per array per chunk
    uint32_t uBh = smem_u32(Bhs) + (uint32_t)nB*(BST*2) + (uint32_t)kg*16;
    uint32_t uBl = smem_u32(Bls) + (uint32_t)nB*(BST*2) + (uint32_t)kg*16;
    const __nv_bfloat16* gBh = Bth + (size_t)(col0 + nB)*KTOT + kg*8;
    const __nv_bfloat16* gBl = Btl + (size_t)(col0 + nB)*KTOT + kg*8;

    // ---- prologue: chunk 0 -> buffer 0 ----
    CP_ASYNC16(uBh, gBh);
    CP_ASYNC16(uBl, gBl);
    CP_COMMIT();

    // ---- stage S ----
    for (int i = tid; i < 2048; i += 512) sS[i] = S[(size_t)row0*8 + i];

    // ---- A fill once: thread tid0 owns row tid0; halves split columns ----
    {
        int tid0 = tid & 255, half = tid >> 8;
        const float* Fp = F + (size_t)(row0 + tid0)*CIN;
        int c0 = half*(CIN/2);
        #pragma unroll
        for (int cc = 0; cc < CIN/2; cc += 4){
            int c = c0 + cc;
            float4 v = *(const float4*)(Fp + c);
            if (USE_BN){
                v.x = fmaxf(fmaf(v.x, ab[c+0], ab[256+c+0]), 0.f);
                v.y = fmaxf(fmaf(v.y, ab[c+1], ab[256+c+1]), 0.f);
                v.z = fmaxf(fmaf(v.z, ab[c+2], ab[256+c+2]), 0.f);
                v.w = fmaxf(fmaf(v.w, ab[c+3], ab[256+c+3]), 0.f);
            }
            __nv_bfloat162 h01 = __floats2bfloat162_rn(v.x, v.y);
            __nv_bfloat162 h23 = __floats2bfloat162_rn(v.z, v.w);
            __nv_bfloat162 l01 = __floats2bfloat162_rn(
                v.x - __bfloat162float(__low2bfloat16(h01)),
                v.y - __bfloat162float(__high2bfloat16(h01)));
            __nv_bfloat162 l23 = __floats2bfloat162_rn(
                v.z - __bfloat162float(__low2bfloat16(h23)),
                v.w - __bfloat162float(__high2bfloat16(h23)));
            int off = tid0*AST + c;
            *(__nv_bfloat162*)&Ah[off]   = h01;
            *(__nv_bfloat162*)&Ah[off+2] = h23;
            *(__nv_bfloat162*)&Al[off]   = l01;
            *(__nv_bfloat162*)&Al[off+2] = l23;
        }
    }

    float acc[2][4][4], acc2[2][4][4];
    #pragma unroll
    for (int i=0;i<2;i++)
        #pragma unroll
        for (int j=0;j<4;j++)
            #pragma unroll
            for (int q=0;q<4;q++){ acc[i][j][q] = 0.f; acc2[i][j][q] = 0.f; }

    CP_WAIT0();
    __syncthreads();

    int it = 0;
    for (int m = 0; m < 8; m++){
        for (int ci = 0; ci < NCH; ci++, it++){
            int nit = it + 1;
            if (nit < NITER){
                uint32_t dof = (nit & 1) ? BUFO : 0u;
                CP_ASYNC16(uBh + dof, gBh + (size_t)nit*64);
                CP_ASYNC16(uBl + dof, gBl + (size_t)nit*64);
                CP_COMMIT();
            }
            uint32_t bo = (it & 1) ? BUFO : 0u;
            #pragma unroll
            for (int kb = 0; kb < 64; kb += 16){
                uint32_t kA = (uint32_t)(ci*64 + kb)*2;
                uint32_t kB = (uint32_t)kb*2;
                uint32_t ah[2][4], al[2][4], bh[4][2], bl[4][2];
                #pragma unroll
                for (int mt=0; mt<2; mt++){
                    LDSM4(ah[mt][0], ah[mt][1], ah[mt][2], ah[mt][3], aAh[mt] + kA);
                    LDSM4(al[mt][0], al[mt][1], al[mt][2], al[mt][3], aAl[mt] + kA);
                }
                LDSM4(bh[0][0], bh[0][1], bh[1][0], bh[1][1], aBh[0] + bo + kB);
                LDSM4(bh[2][0], bh[2][1], bh[3][0], bh[3][1], aBh[1] + bo + kB);
                LDSM4(bl[0][0], bl[0][1], bl[1][0], bl[1][1], aBl[0] + bo + kB);
                LDSM4(bl[2][0], bl[2][1], bl[3][0], bl[3][1], aBl[1] + bo + kB);
                #pragma unroll
                for (int mt=0; mt<2; mt++)
                    #pragma unroll
                    for (int nt=0; nt<4; nt++){
                        float* d = acc[mt][nt];
                        asm volatile(
                          "mma.sync.aligned.m16n8k16.row.col.f32.bf16.bf16.f32 "
                          "{%0,%1,%2,%3}, {%4,%5,%6,%7}, {%8,%9}, {%0,%1,%2,%3};"
                          : "+f"(d[0]),"+f"(d[1]),"+f"(d[2]),"+f"(d[3])
                          : "r"(ah[mt][0]),"r"(ah[mt][1]),"r"(ah[mt][2]),"r"(ah[mt][3]),
                            "r"(bh[nt][0]),"r"(bh[nt][1]));
                        asm volatile(
                          "mma.sync.aligned.m16n8k16.row.col.f32.bf16.bf16.f32 "
                          "{%0,%1,%2,%3}, {%4,%5,%6,%7}, {%8,%9}, {%0,%1,%2,%3};"
                          : "+f"(d[0]),"+f"(d[1]),"+f"(d[2]),"+f"(d[3])
                          : "r"(ah[mt][0]),"r"(ah[mt][1]),"r"(ah[mt][2]),"r"(ah[mt][3]),
                            "r"(bl[nt][0]),"r"(bl[nt][1]));
                        asm volatile(
                          "mma.sync.aligned.m16n8k16.row.col.f32.bf16.bf16.f32 "
                          "{%0,%1,%2,%3}, {%4,%5,%6,%7}, {%8,%9}, {%0,%1,%2,%3};"
                          : "+f"(d[0]),"+f"(d[1]),"+f"(d[2]),"+f"(d[3])
                          : "r"(al[mt][0]),"r"(al[mt][1]),"r"(al[mt][2]),"r"(al[mt][3]),
                            "r"(bh[nt][0]),"r"(bh[nt][1]));
                    }
            }
            // ---- fold acc into acc2 with s[row, m] at end of m ----
            if (ci == NCH-1){
                #pragma unroll
                for (int mt=0; mt<2; mt++){
                    int r = wr*32 + mt*16 + gr;
                    float s0 = sS[r*8 + m];
                    float s1 = sS[(r+8)*8 + m];
                    #pragma unroll
                    for (int nt=0; nt<4; nt++){
                        acc2[mt][nt][0] = fmaf(s0, acc[mt][nt][0], acc2[mt][nt][0]);
                        acc2[mt][nt][1] = fmaf(s0, acc[mt][nt][1], acc2[mt][nt][1]);
                        acc2[mt][nt][2] = fmaf(s1, acc[mt][nt][2], acc2[mt][nt][2]);
                        acc2[mt][nt][3] = fmaf(s1, acc[mt][nt][3], acc2[mt][nt][3]);
                        acc[mt][nt][0]=0.f; acc[mt][nt][1]=0.f; acc[mt][nt][2]=0.f; acc[mt][nt][3]=0.f;
                    }
                }
            }
            if (nit < NITER) CP_WAIT0();
            __syncthreads();
        }
    }

    // ---- epilogue ----
    if (FUSE_MAX){
        // rows wr*32+mt*16 .. +15 form one p-group (16 k values); reduce in-register.
        #pragma unroll
        for (int mt=0; mt<2; mt++){
            int pg = (row0 + wr*32 + mt*16) >> 4;   // = b*512 + p
            int bb = pg >> 9, pp = pg & 511;
            #pragma unroll
            for (int nt=0; nt<4; nt++){
                float v0 = fmaxf(acc2[mt][nt][0], acc2[mt][nt][2]);
                float v1 = fmaxf(acc2[mt][nt][1], acc2[mt][nt][3]);
                #pragma unroll
                for (int off=4; off<=16; off<<=1){
                    v0 = fmaxf(v0, __shfl_xor_sync(0xffffffffu, v0, off));
                    v1 = fmaxf(v1, __shfl_xor_sync(0xffffffffu, v1, off));
                }
                if (gr == 0){
                    int c = col0 + wc*32 + nt*8 + qc;
                    O[((size_t)bb*256 + c)*NP + pp]     = v0;
                    O[((size_t)bb*256 + c+1)*NP + pp]   = v1;
                }
            }
        }
    } else {
        #pragma unroll
        for (int mt=0; mt<2; mt++){
            int r = row0 + wr*32 + mt*16 + gr;
            #pragma unroll
            for (int nt=0; nt<4; nt++){
                int c = col0 + wc*32 + nt*8 + qc;
                float* d = acc2[mt][nt];
                *(float2*)&O[(size_t)r*COUT + c]     = make_float2(d[0], d[1]);
                *(float2*)&O[(size_t)(r+8)*COUT + c] = make_float2(d[2], d[3]);
            }
        }
    }
}

// ---------------- BN stats: deterministic two-stage ----------------
template<int C>
__global__ void bn_stats1(const float* __restrict__ O){
    __shared__ float sm1[256], sm2[256];
    int tid = threadIdx.x;
    float s1 = 0.f, s2 = 0.f;
    for (int i = blockIdx.x*256 + tid; i < ROWS*C; i += 65536){
        float v = O[i]; s1 += v; s2 += v*v;
    }
    sm1[tid] = s1; sm2[tid] = s2; __syncthreads();
    if (tid < C){
        for (int j = tid + C; j < 256; j += C){ s1 += sm1[j]; s2 += sm2[j]; }
        d_part[(blockIdx.x*C + tid)*2]   = s1;
        d_part[(blockIdx.x*C + tid)*2+1] = s2;
    }
}

template<int C>
__global__ void bn_stats2(const float* __restrict__ gamma, const float* __restrict__ beta){
    int c = threadIdx.x;
    double s1 = 0.0, s2 = 0.0;
    for (int j=0;j<256;j++){
        s1 += (double)d_part[(j*C + c)*2];
        s2 += (double)d_part[(j*C + c)*2 + 1];
    }
    double mean = s1 / 65536.0;
    double var  = s2 / 65536.0 - mean*mean;
    float a = (float)((double)gamma[c] / sqrt(var + 1e-5));
    d_ab[c]       = a;
    d_ab[256 + c] = beta[c] - (float)mean * a;
}

// ---------------- launch ----------------
extern "C" void kernel_launch(void* const* d_in, const int* in_sizes, int n_in,
                              void* d_out, int out_size){
    const float* xyz   = (const float*)d_in[0];
    const float* nr    = (const float*)d_in[1];
    const float* Xa    = (const float*)d_in[2];
    const float* Ya    = (const float*)d_in[3];
    const float* pts   = (const float*)d_in[4];
    const float* w1_0  = (const float*)d_in[5];
    const float* b1_0  = (const float*)d_in[6];
    const float* w2_0  = (const float*)d_in[7];
    const float* b2_0  = (const float*)d_in[8];
    const float* bank0 = (const float*)d_in[9];
    const float* gam0  = (const float*)d_in[10];
    const float* bet0  = (const float*)d_in[11];
    const float* w1_1  = (const float*)d_in[12];
    const float* b1_1  = (const float*)d_in[13];
    const float* w2_1  = (const float*)d_in[14];
    const float* b2_1  = (const float*)d_in[15];
    const float* bank1 = (const float*)d_in[16];
    const float* gam1  = (const float*)d_in[17];
    const float* bet1  = (const float*)d_in[18];
    const float* w1_2  = (const float*)d_in[19];
    const float* b1_2  = (const float*)d_in[20];
    const float* w2_2  = (const float*)d_in[21];
    const float* b2_2  = (const float*)d_in[22];
    const float* bank2 = (const float*)d_in[23];
    float* out = (float*)d_out;

    float *pF0, *pO0, *pO1, *pS, *pab;
    __nv_bfloat16 *pBH0, *pBL0, *pBH1, *pBL1, *pBH2, *pBL2;
    cudaGetSymbolAddress((void**)&pF0, d_F0);
    cudaGetSymbolAddress((void**)&pO0, d_O0);
    cudaGetSymbolAddress((void**)&pO1, d_O1);
    cudaGetSymbolAddress((void**)&pS,  d_S);
    cudaGetSymbolAddress((void**)&pab, d_ab);
    cudaGetSymbolAddress((void**)&pBH0, d_bh0);
    cudaGetSymbolAddress((void**)&pBL0, d_bl0);
    cudaGetSymbolAddress((void**)&pBH1, d_bh1);
    cudaGetSymbolAddress((void**)&pBL1, d_bl1);
    cudaGetSymbolAddress((void**)&pBH2, d_bh2);
    cudaGetSymbolAddress((void**)&pBL2, d_bl2);

    const int SMA64  = 2*(256*72*2)  + 2*(2*64*BST*2) + 8192;   // 155648
    const int SMA128 = 2*(256*136*2) + 2*(2*64*BST*2) + 8192;   // 221184
    cudaFuncSetAttribute(paconv_mma<64,64,false,false>,  cudaFuncAttributeMaxDynamicSharedMemorySize, SMA64);
    cudaFuncSetAttribute(paconv_mma<64,128,true,false>,  cudaFuncAttributeMaxDynamicSharedMemorySize, SMA64);
    cudaFuncSetAttribute(paconv_mma<128,256,true,true>,  cudaFuncAttributeMaxDynamicSharedMemorySize, SMA128);

    fps_bsplit_kernel<<<1416,256>>>(xyz, out, bank0, bank1, bank2);  // 1 (fps + bank split fused)
    ptsT_kernel<<<dim3(64,8),256>>>(pts);                            // 2 (pts -> n-major)
    knn_kernel<<<512,256>>>(xyz);                                    // 3
    geomS_kernel<<<512,128>>>(xyz, nr, Xa, Ya, out,
        w1_0,b1_0,w2_0,b2_0, w1_1,b1_1,w2_1,b2_1, w1_2,b1_2,w2_2,b2_2); // 4 <- ncu
    paconv_mma<64,64,false,false><<<dim3(256,1),512,SMA64>>>(pF0, pS, pBH0, pBL0, pab, pO0);  // 5
    bn_stats1<64><<<256,256>>>(pO0);                                 // 6
    bn_stats2<64><<<1,64>>>(gam0, bet0);                             // 7
    paconv_mma<64,128,true,false><<<dim3(256,2),512,SMA64>>>(pO0, pS + ROWS*8, pBH1, pBL1, pab, pO1); // 8
    bn_stats1<128><<<256,256>>>(pO1);                                // 9
    bn_stats2<128><<<1,128>>>(gam1, bet1);                           // 10
    paconv_mma<128,256,true,true><<<dim3(256,4),512,SMA128>>>(pO1, pS + 2*ROWS*8, pBH2, pBL2, pab,
                                                              out + 4*3*BB*NP); // 11 (fused max)
}